// round 10
// baseline (speedup 1.0000x reference)
#include <cuda_runtime.h>
#include <math.h>

// Swin stage: B=4, H=W=256, C=96, NH=6, HD=16, WS=8, N=64; 4096 windows.
// Split kernels (proven better occupancy profile than full fusion):
//   attn_kernel: LN1 + QKV + warp-autonomous attention + proj + residual
//   mlp_kernel:  LN2 + fc1/gelu/fc2 + residual (2 CTAs/SM)
// All GEMMs tf32 mma.sync.m16n8k8; weights pre-packed in fragment order.

#define W_ELEMS   221184             // packed tf32 weights, both layers

__device__ float g_w[W_ELEMS];       // packed tf32 weights

#define OFF_QKV0   0
#define OFF_QKV1   27648
#define OFF_PROJ0  55296
#define OFF_PROJ1  64512
#define OFF_F1_0   73728
#define OFF_F1_1   110592
#define OFF_F2_0   147456
#define OFF_F2_1   184320

__device__ __forceinline__ unsigned f2tf(float f) {
    unsigned u; asm("cvt.rna.tf32.f32 %0, %1;" : "=r"(u) : "f"(f)); return u;
}
__device__ __forceinline__ float tf32f(float f) {
    return __uint_as_float(f2tf(f));
}
__device__ __forceinline__ void mma_tf32(float* c, const unsigned* a, const unsigned* b) {
    asm volatile(
        "mma.sync.aligned.m16n8k8.row.col.f32.tf32.tf32.f32 "
        "{%0,%1,%2,%3},{%4,%5,%6,%7},{%8,%9},{%0,%1,%2,%3};\n"
        : "+f"(c[0]), "+f"(c[1]), "+f"(c[2]), "+f"(c[3])
        : "r"(a[0]), "r"(a[1]), "r"(a[2]), "r"(a[3]), "r"(b[0]), "r"(b[1]));
}

// ---- weight packer: W(O,K) row-major -> per-fragment tf32 layout ----
__global__ void pack_w(const float* __restrict__ src, float* __restrict__ dst,
                       int O, int K) {
    int idx = blockIdx.x * 256 + threadIdx.x;
    if (idx >= O * K) return;
    int j    = idx & 1;
    int lane = (idx >> 1) & 31;
    int rest = idx >> 6;
    int KS   = K >> 3;
    int kk   = rest % KS;
    int nt   = rest / KS;
    int n = nt * 8 + (lane >> 2);
    int k = kk * 8 + (lane & 3) + j * 4;
    dst[idx] = __uint_as_float(f2tf(src[n * K + k]));
}

// ======================= attention kernel =======================
// smem (floats): xs[64*100]=6400 | qk[18*64*20]=23040 | P[8*16*68]=8704
#define ATTN_SMEM_FLOATS (6400 + 23040 + 8704)

__global__ void __launch_bounds__(256) attn_kernel(
    const float* __restrict__ xin, float* __restrict__ xout,
    const float* __restrict__ wqkv, const float* __restrict__ qkvb,
    const float* __restrict__ wproj, const float* __restrict__ projb,
    const float* __restrict__ rpb,
    const float* __restrict__ g1, const float* __restrict__ bb1,
    int shift)
{
    extern __shared__ float sm[];
    float* xs   = sm;             // 64 x 100 : LN'd x -> attention ctx
    float* qk   = sm + 6400;      // [18][64][20] q,k,v
    float* Pbuf = sm + 29440;     // 8 warps x 16 x 68 probs

    const int tid = threadIdx.x, lane = tid & 31, wid = tid >> 5;
    const int g = lane >> 2, tg = lane & 3;
    const int wm = wid >> 1, wn = wid & 1;
    const int m0 = wm * 16;

    const int win = blockIdx.x;
    const int b = win >> 10, wi = win & 1023, wh = wi >> 5, ww = wi & 31;

    // ---------- phase 1: LN1 (4 threads/token) ----------
    {
        int t = tid >> 2, l4 = tid & 3;
        int th = t >> 3, tw = t & 7;
        int h0 = (wh*8 + th + shift) & 255, w0 = (ww*8 + tw + shift) & 255;
        const float* xr = xin + ((size_t)b*65536 + (size_t)h0*256 + w0)*96;
        float vals[24], s = 0.f, ss = 0.f;
        #pragma unroll
        for (int j = 0; j < 24; j++) {
            float v = xr[l4 + 4*j]; vals[j] = v; s += v; ss += v*v;
        }
        s  += __shfl_xor_sync(0xffffffffu, s, 1);
        s  += __shfl_xor_sync(0xffffffffu, s, 2);
        ss += __shfl_xor_sync(0xffffffffu, ss, 1);
        ss += __shfl_xor_sync(0xffffffffu, ss, 2);
        float mean = s * (1.f/96.f);
        float rstd = rsqrtf(ss * (1.f/96.f) - mean*mean + 1e-5f);
        #pragma unroll
        for (int j = 0; j < 24; j++) {
            int c = l4 + 4*j;
            xs[t*100 + c] = tf32f((vals[j]-mean)*rstd*g1[c] + bb1[c]);
        }
    }
    __syncthreads();

    // ---------- phase 2: QKV GEMM ----------
    {
        unsigned Af[12][4];
        #pragma unroll
        for (int kk = 0; kk < 12; kk++) {
            int base = (m0+g)*100 + kk*8 + tg;
            Af[kk][0] = __float_as_uint(xs[base]);
            Af[kk][1] = __float_as_uint(xs[base + 800]);
            Af[kk][2] = __float_as_uint(xs[base + 4]);
            Af[kk][3] = __float_as_uint(xs[base + 804]);
        }
        for (int s3 = 0; s3 < 3; s3++) {
            float acc[6][4];
            #pragma unroll
            for (int i = 0; i < 6; i++) { acc[i][0]=acc[i][1]=acc[i][2]=acc[i][3]=0.f; }
            for (int kk = 0; kk < 12; kk++) {
                #pragma unroll
                for (int nt = 0; nt < 6; nt++) {
                    int ntg = s3*12 + wn*6 + nt;
                    float2 bv = *(const float2*)&wqkv[((ntg*12 + kk)*32 + lane)*2];
                    unsigned bb[2] = { __float_as_uint(bv.x), __float_as_uint(bv.y) };
                    mma_tf32(acc[nt], Af[kk], bb);
                }
            }
            #pragma unroll
            for (int nt = 0; nt < 6; nt++) {
                #pragma unroll
                for (int i = 0; i < 2; i++) {
                    #pragma unroll
                    for (int j = 0; j < 2; j++) {
                        int ncol = wn*48 + nt*8 + 2*tg + j;
                        int hh = ncol >> 4, d = ncol & 15;
                        int m = m0 + g + i*8;
                        float v = acc[nt][i*2+j] + __ldg(&qkvb[s3*96 + ncol]);
                        if (s3 == 0) v *= 0.25f;
                        qk[(s3*6 + hh)*1280 + m*20 + d] = tf32f(v);
                    }
                }
            }
        }
    }
    __syncthreads();

    // ---------- phase 3: attention, warp-autonomous ----------
    // 24 tasks = 6 heads x 4 row-blocks; warp w does tasks w, w+8, w+16.
    {
        float* Pw = Pbuf + wid * 1088;   // 16 x 68
        #pragma unroll
        for (int it = 0; it < 3; it++) {
            int task = it*8 + wid;
            int h = task >> 2, r = task & 3;
            int row0 = r * 16;
            const float* qh = qk + h*1280;
            const float* kh = qk + (6+h)*1280;
            const float* vh = qk + (12+h)*1280;

            unsigned Aq[2][4];
            #pragma unroll
            for (int kk = 0; kk < 2; kk++) {
                int base = (row0+g)*20 + kk*8 + tg;
                Aq[kk][0] = __float_as_uint(qh[base]);
                Aq[kk][1] = __float_as_uint(qh[base + 160]);
                Aq[kk][2] = __float_as_uint(qh[base + 4]);
                Aq[kk][3] = __float_as_uint(qh[base + 164]);
            }
            float acc[8][4];
            #pragma unroll
            for (int i = 0; i < 8; i++) { acc[i][0]=acc[i][1]=acc[i][2]=acc[i][3]=0.f; }
            #pragma unroll
            for (int kk = 0; kk < 2; kk++) {
                #pragma unroll
                for (int nt = 0; nt < 8; nt++) {
                    unsigned bb[2] = {
                        __float_as_uint(kh[(nt*8+g)*20 + kk*8 + tg]),
                        __float_as_uint(kh[(nt*8+g)*20 + kk*8 + tg + 4]) };
                    mma_tf32(acc[nt], Aq[kk], bb);
                }
            }
            // bias + mask
            #pragma unroll
            for (int nt = 0; nt < 8; nt++) {
                #pragma unroll
                for (int i = 0; i < 2; i++) {
                    #pragma unroll
                    for (int j = 0; j < 2; j++) {
                        int t = row0 + g + i*8;
                        int u = nt*8 + 2*tg + j;
                        int ti = t>>3, tj = t&7, ui = u>>3, uj = u&7;
                        float d = acc[nt][i*2+j]
                                + __ldg(&rpb[((ti-ui+7)*15 + (tj-uj+7))*6 + h]);
                        if (shift) {
                            int hrt = wh*8+ti, wrt = ww*8+tj;
                            int hru = wh*8+ui, wru = ww*8+uj;
                            int rt = (hrt<248?0:(hrt<252?1:2))*3 + (wrt<248?0:(wrt<252?1:2));
                            int ru = (hru<248?0:(hru<252?1:2))*3 + (wru<248?0:(wru<252?1:2));
                            if (rt != ru) d -= 100.f;
                        }
                        acc[nt][i*2+j] = d;
                    }
                }
            }
            // softmax per row; 64 cols live in the 4 tg-lanes of the quad
            #pragma unroll
            for (int i = 0; i < 2; i++) {
                float mx = -1e30f;
                #pragma unroll
                for (int nt = 0; nt < 8; nt++)
                    mx = fmaxf(mx, fmaxf(acc[nt][i*2], acc[nt][i*2+1]));
                mx = fmaxf(mx, __shfl_xor_sync(0xffffffffu, mx, 1));
                mx = fmaxf(mx, __shfl_xor_sync(0xffffffffu, mx, 2));
                float sum = 0.f;
                #pragma unroll
                for (int nt = 0; nt < 8; nt++) {
                    float e0 = __expf(acc[nt][i*2]   - mx);
                    float e1 = __expf(acc[nt][i*2+1] - mx);
                    acc[nt][i*2] = e0; acc[nt][i*2+1] = e1;
                    sum += e0 + e1;
                }
                sum += __shfl_xor_sync(0xffffffffu, sum, 1);
                sum += __shfl_xor_sync(0xffffffffu, sum, 2);
                float inv = 1.f / sum;
                int lr = g + i*8;
                #pragma unroll
                for (int nt = 0; nt < 8; nt++) {
                    Pw[lr*68 + nt*8 + 2*tg]     = tf32f(acc[nt][i*2]   * inv);
                    Pw[lr*68 + nt*8 + 2*tg + 1] = tf32f(acc[nt][i*2+1] * inv);
                }
            }
            __syncwarp();
            // AV: 16 x 16
            float av[2][4];
            av[0][0]=av[0][1]=av[0][2]=av[0][3]=0.f;
            av[1][0]=av[1][1]=av[1][2]=av[1][3]=0.f;
            #pragma unroll
            for (int kk = 0; kk < 8; kk++) {
                int base = g*68 + kk*8 + tg;
                unsigned Ap[4] = {
                    __float_as_uint(Pw[base]),
                    __float_as_uint(Pw[base + 544]),
                    __float_as_uint(Pw[base + 4]),
                    __float_as_uint(Pw[base + 548]) };
                #pragma unroll
                for (int nt = 0; nt < 2; nt++) {
                    unsigned bb[2] = {
                        __float_as_uint(vh[(kk*8+tg)*20   + nt*8 + g]),
                        __float_as_uint(vh[(kk*8+tg+4)*20 + nt*8 + g]) };
                    mma_tf32(av[nt], Ap, bb);
                }
            }
            #pragma unroll
            for (int nt = 0; nt < 2; nt++)
                #pragma unroll
                for (int i = 0; i < 2; i++)
                    #pragma unroll
                    for (int j = 0; j < 2; j++)
                        xs[(row0+g+i*8)*100 + h*16 + nt*8 + 2*tg + j] =
                            tf32f(av[nt][i*2+j]);
            __syncwarp();
        }
    }
    __syncthreads();

    // ---------- phase 4: proj + residual -> gmem ----------
    {
        unsigned Ac[12][4];
        #pragma unroll
        for (int kk = 0; kk < 12; kk++) {
            int base = (m0+g)*100 + kk*8 + tg;
            Ac[kk][0] = __float_as_uint(xs[base]);
            Ac[kk][1] = __float_as_uint(xs[base + 800]);
            Ac[kk][2] = __float_as_uint(xs[base + 4]);
            Ac[kk][3] = __float_as_uint(xs[base + 804]);
        }
        float acc[6][4];
        #pragma unroll
        for (int i = 0; i < 6; i++) { acc[i][0]=acc[i][1]=acc[i][2]=acc[i][3]=0.f; }
        for (int kk = 0; kk < 12; kk++) {
            #pragma unroll
            for (int nt = 0; nt < 6; nt++) {
                int ntg = wn*6 + nt;
                float2 bv = *(const float2*)&wproj[((ntg*12 + kk)*32 + lane)*2];
                unsigned bb[2] = { __float_as_uint(bv.x), __float_as_uint(bv.y) };
                mma_tf32(acc[nt], Ac[kk], bb);
            }
        }
        #pragma unroll
        for (int nt = 0; nt < 6; nt++) {
            #pragma unroll
            for (int i = 0; i < 2; i++) {
                int ncol0 = wn*48 + nt*8 + 2*tg;
                int m = m0 + g + i*8;
                int th = m >> 3, tw = m & 7;
                int h0 = (wh*8 + th + shift) & 255;
                int w0 = (ww*8 + tw + shift) & 255;
                size_t row = ((size_t)b*65536 + (size_t)h0*256 + w0)*96;
                float2 rr = *(const float2*)&xin[row + ncol0];
                float2 o;
                o.x = rr.x + acc[nt][i*2]   + __ldg(&projb[ncol0]);
                o.y = rr.y + acc[nt][i*2+1] + __ldg(&projb[ncol0+1]);
                *(float2*)&xout[row + ncol0] = o;
            }
        }
    }
}

// ======================= MLP kernel (round-4 verbatim) =======================
// smem: xs[64*100]=6400 | yb[64*100]=6400
#define MLP_SMEM_FLOATS (6400 + 6400)

__global__ void __launch_bounds__(256, 2) mlp_kernel(
    const float* __restrict__ xin, float* __restrict__ xout,
    const float* __restrict__ g2, const float* __restrict__ bb2,
    const float* __restrict__ w1p, const float* __restrict__ b1v,
    const float* __restrict__ w2p, const float* __restrict__ b2v)
{
    extern __shared__ float sm[];
    float* xs = sm;          // 64 x 100 LN'd (tf32)
    float* yb = sm + 6400;   // 64 x 100 gelu(fc1) chunk (tf32)

    const int tid = threadIdx.x, lane = tid & 31, wid = tid >> 5;
    const int g = lane >> 2, tg = lane & 3;
    const int wm = wid >> 1, wn = wid & 1;
    const int m0 = wm * 16;
    const size_t base = (size_t)blockIdx.x * 64 * 96;

    // LN2
    {
        int t = tid >> 2, l4 = tid & 3;
        const float* xr = xin + base + (size_t)t*96;
        float vals[24], s = 0.f, ss = 0.f;
        #pragma unroll
        for (int j = 0; j < 24; j++) {
            float v = xr[l4 + 4*j]; vals[j] = v; s += v; ss += v*v;
        }
        s  += __shfl_xor_sync(0xffffffffu, s, 1);
        s  += __shfl_xor_sync(0xffffffffu, s, 2);
        ss += __shfl_xor_sync(0xffffffffu, ss, 1);
        ss += __shfl_xor_sync(0xffffffffu, ss, 2);
        float mean = s * (1.f/96.f);
        float rstd = rsqrtf(ss * (1.f/96.f) - mean*mean + 1e-5f);
        #pragma unroll
        for (int j = 0; j < 24; j++) {
            int c = l4 + 4*j;
            xs[t*100 + c] = tf32f((vals[j]-mean)*rstd*g2[c] + bb2[c]);
        }
    }
    __syncthreads();

    unsigned Af[12][4];
    #pragma unroll
    for (int kk = 0; kk < 12; kk++) {
        int bse = (m0+g)*100 + kk*8 + tg;
        Af[kk][0] = __float_as_uint(xs[bse]);
        Af[kk][1] = __float_as_uint(xs[bse + 800]);
        Af[kk][2] = __float_as_uint(xs[bse + 4]);
        Af[kk][3] = __float_as_uint(xs[bse + 804]);
    }

    float acc2[6][4];
    #pragma unroll
    for (int i = 0; i < 6; i++) { acc2[i][0]=acc2[i][1]=acc2[i][2]=acc2[i][3]=0.f; }

    for (int ch = 0; ch < 4; ch++) {
        float acc[6][4];
        #pragma unroll
        for (int i = 0; i < 6; i++) { acc[i][0]=acc[i][1]=acc[i][2]=acc[i][3]=0.f; }
        for (int kk = 0; kk < 12; kk++) {
            #pragma unroll
            for (int nt = 0; nt < 6; nt++) {
                int ntg = ch*12 + wn*6 + nt;
                float2 bv = *(const float2*)&w1p[((ntg*12 + kk)*32 + lane)*2];
                unsigned bb[2] = { __float_as_uint(bv.x), __float_as_uint(bv.y) };
                mma_tf32(acc[nt], Af[kk], bb);
            }
        }
        #pragma unroll
        for (int nt = 0; nt < 6; nt++) {
            #pragma unroll
            for (int i = 0; i < 2; i++) {
                #pragma unroll
                for (int j = 0; j < 2; j++) {
                    int c = wn*48 + nt*8 + 2*tg + j;
                    float v = acc[nt][i*2+j] + __ldg(&b1v[ch*96 + c]);
                    v = v * normcdff(v);
                    yb[(m0+g+i*8)*100 + c] = tf32f(v);
                }
            }
        }
        __syncthreads();
        for (int kk = 0; kk < 12; kk++) {
            int bse = (m0+g)*100 + kk*8 + tg;
            unsigned Ay[4] = {
                __float_as_uint(yb[bse]),
                __float_as_uint(yb[bse + 800]),
                __float_as_uint(yb[bse + 4]),
                __float_as_uint(yb[bse + 804]) };
            #pragma unroll
            for (int nt = 0; nt < 6; nt++) {
                int ntg = wn*6 + nt;
                int kkg = ch*12 + kk;
                float2 bv = *(const float2*)&w2p[((ntg*48 + kkg)*32 + lane)*2];
                unsigned bb[2] = { __float_as_uint(bv.x), __float_as_uint(bv.y) };
                mma_tf32(acc2[nt], Ay, bb);
            }
        }
        __syncthreads();
    }

    // residual writeback
    #pragma unroll
    for (int nt = 0; nt < 6; nt++) {
        #pragma unroll
        for (int i = 0; i < 2; i++) {
            int c0 = wn*48 + nt*8 + 2*tg;
            int m = m0 + g + i*8;
            float2 r = *(const float2*)&xin[base + (size_t)m*96 + c0];
            float2 o;
            o.x = r.x + acc2[nt][i*2]   + __ldg(&b2v[c0]);
            o.y = r.y + acc2[nt][i*2+1] + __ldg(&b2v[c0+1]);
            *(float2*)&xout[base + (size_t)m*96 + c0] = o;
        }
    }
}

// ======================= launcher =======================
extern "C" void kernel_launch(void* const* d_in, const int* in_sizes, int n_in,
                              void* d_out, int out_size) {
    const float* x    = (const float*)d_in[0];
    const float* qkvw = (const float*)d_in[1];   // (2,288,96)
    const float* qkvb = (const float*)d_in[2];   // (2,288)
    const float* projw= (const float*)d_in[3];   // (2,96,96)
    const float* projb= (const float*)d_in[4];   // (2,96)
    const float* rpb  = (const float*)d_in[5];   // (2,225,6)
    const float* n1w  = (const float*)d_in[6];
    const float* n1b  = (const float*)d_in[7];
    const float* n2w  = (const float*)d_in[8];
    const float* n2b  = (const float*)d_in[9];
    const float* f1w  = (const float*)d_in[10];  // (2,384,96)
    const float* f1b  = (const float*)d_in[11];  // (2,384)
    const float* f2w  = (const float*)d_in[12];  // (2,96,384)
    const float* f2b  = (const float*)d_in[13];  // (2,96)
    float* out = (float*)d_out;

    float* gw = nullptr;  cudaGetSymbolAddress((void**)&gw, g_w);

    // ---- pack weights to tf32 fragment order ----
    pack_w<<<108, 256>>>(qkvw,          gw + OFF_QKV0, 288, 96);
    pack_w<<<108, 256>>>(qkvw + 27648,  gw + OFF_QKV1, 288, 96);
    pack_w<<<36,  256>>>(projw,         gw + OFF_PROJ0, 96, 96);
    pack_w<<<36,  256>>>(projw + 9216,  gw + OFF_PROJ1, 96, 96);
    pack_w<<<144, 256>>>(f1w,           gw + OFF_F1_0, 384, 96);
    pack_w<<<144, 256>>>(f1w + 36864,   gw + OFF_F1_1, 384, 96);
    pack_w<<<144, 256>>>(f2w,           gw + OFF_F2_0, 96, 384);
    pack_w<<<144, 256>>>(f2w + 36864,   gw + OFF_F2_1, 96, 384);

    const int ATTN_SMEM = ATTN_SMEM_FLOATS * 4;   // 152576 B
    const int MLP_SMEM  = MLP_SMEM_FLOATS * 4;    // 51200 B
    cudaFuncSetAttribute(attn_kernel, cudaFuncAttributeMaxDynamicSharedMemorySize, ATTN_SMEM);
    cudaFuncSetAttribute(mlp_kernel,  cudaFuncAttributeMaxDynamicSharedMemorySize, MLP_SMEM);

    const int NBLK = 4096;

    // All stages in-place on out (window/token bijection makes each CTA
    // read-only-what-it-writes). No scratch buffer needed.
    attn_kernel<<<NBLK, 256, ATTN_SMEM>>>(x, out,
        gw + OFF_QKV0, qkvb, gw + OFF_PROJ0, projb, rpb, n1w, n1b, 0);
    mlp_kernel<<<NBLK, 256, MLP_SMEM>>>(out, out,
        n2w, n2b, gw + OFF_F1_0, f1b, gw + OFF_F2_0, f2b);

    attn_kernel<<<NBLK, 256, ATTN_SMEM>>>(out, out,
        gw + OFF_QKV1, qkvb + 288, gw + OFF_PROJ1, projb + 96,
        rpb + 225*6, n1w + 96, n1b + 96, 4);
    mlp_kernel<<<NBLK, 256, MLP_SMEM>>>(out, out,
        n2w + 96, n2b + 96, gw + OFF_F1_1, f1b + 384, gw + OFF_F2_1, f2b + 96);
}

// round 11
// speedup vs baseline: 1.5004x; 1.5004x over previous
#include <cuda_runtime.h>
#include <math.h>

// Swin stage: B=4, H=W=256, C=96, NH=6, HD=16, WS=8, N=64; 4096 windows.
// Round-4 structure (measured best): split attn/mlp, CTA-barrier attention.
// This round: XOR-swizzled compact smem layout in attn (114,688 B) -> 2 CTAs/SM.
// All GEMMs tf32 mma.sync.m16n8k8; weights pre-packed in fragment order.

#define W_ELEMS   221184

__device__ float g_w[W_ELEMS];

#define OFF_QKV0   0
#define OFF_QKV1   27648
#define OFF_PROJ0  55296
#define OFF_PROJ1  64512
#define OFF_F1_0   73728
#define OFF_F1_1   110592
#define OFF_F2_0   147456
#define OFF_F2_1   184320

__device__ __forceinline__ unsigned f2tf(float f) {
    unsigned u; asm("cvt.rna.tf32.f32 %0, %1;" : "=r"(u) : "f"(f)); return u;
}
__device__ __forceinline__ float tf32f(float f) {
    return __uint_as_float(f2tf(f));
}
__device__ __forceinline__ void mma_tf32(float* c, const unsigned* a, const unsigned* b) {
    asm volatile(
        "mma.sync.aligned.m16n8k8.row.col.f32.tf32.tf32.f32 "
        "{%0,%1,%2,%3},{%4,%5,%6,%7},{%8,%9},{%0,%1,%2,%3};\n"
        : "+f"(c[0]), "+f"(c[1]), "+f"(c[2]), "+f"(c[3])
        : "r"(a[0]), "r"(a[1]), "r"(a[2]), "r"(a[3]), "r"(b[0]), "r"(b[1]));
}

// XOR swizzle: rows r and r+8 share the same swizzle; banks spread as with padding.
#define SWZ(r, c) ((c) ^ (((r) & 7) << 2))

// ---- merged weight packer: all 8 regions in one launch ----
__global__ void pack_all(const float* __restrict__ qkvw, const float* __restrict__ projw,
                         const float* __restrict__ f1w,  const float* __restrict__ f2w,
                         float* __restrict__ dst) {
    int idx = blockIdx.x * 256 + threadIdx.x;
    if (idx >= W_ELEMS) return;
    const float* src; int O, K, local;
    if (idx < 55296)       { int r = idx;          src = qkvw  + (r/27648)*27648; O=288; K=96;  local = r % 27648; }
    else if (idx < 73728)  { int r = idx - 55296;  src = projw + (r/9216)*9216;   O=96;  K=96;  local = r % 9216; }
    else if (idx < 147456) { int r = idx - 73728;  src = f1w   + (r/36864)*36864; O=384; K=96;  local = r % 36864; }
    else                   { int r = idx - 147456; src = f2w   + (r/36864)*36864; O=96;  K=384; local = r % 36864; }
    int j    = local & 1;
    int lane = (local >> 1) & 31;
    int rest = local >> 6;
    int KS   = K >> 3;
    int kk   = rest % KS;
    int nt   = rest / KS;
    int n = nt * 8 + (lane >> 2);
    int k = kk * 8 + (lane & 3) + j * 4;
    (void)O;
    dst[idx] = __uint_as_float(f2tf(src[n * K + k]));
}

// ======================= attention kernel =======================
// smem (floats, all XOR-swizzled): xs[64][96]=6144 | qkv[64][288]=18432 | sc[64][64]=4096
// total 28672 floats = 114688 B  ->  2 CTAs/SM
#define ATTN_SMEM_FLOATS (6144 + 18432 + 4096)

__global__ void __launch_bounds__(256, 2) attn_kernel(
    const float* __restrict__ xin, float* __restrict__ xout,
    const float* __restrict__ wqkv, const float* __restrict__ qkvb,
    const float* __restrict__ wproj, const float* __restrict__ projb,
    const float* __restrict__ rpb,
    const float* __restrict__ g1, const float* __restrict__ bb1,
    int shift)
{
    extern __shared__ float sm[];
    float* xs = sm;            // [64][96]  LN'd x -> attention ctx
    float* qk = sm + 6144;     // [64][288] q(0-95, pre-scaled) k(96-191) v(192-287)
    float* sc = sm + 24576;    // [64][64]  scores / probs

    const int tid = threadIdx.x, lane = tid & 31, wid = tid >> 5;
    const int g = lane >> 2, tg = lane & 3;
    const int wm = wid >> 1, wn = wid & 1;
    const int m0 = wm * 16;
    const int sw = g << 2;     // row-swizzle for rows m0+g (+8): (m0+g)&7 == g

    const int win = blockIdx.x;
    const int b = win >> 10, wi = win & 1023, wh = wi >> 5, ww = wi & 31;

    // ---------- phase 1: LN1 (4 threads/token) ----------
    {
        int t = tid >> 2, l4 = tid & 3;
        int th = t >> 3, tw = t & 7;
        int h0 = (wh*8 + th + shift) & 255, w0 = (ww*8 + tw + shift) & 255;
        const float* xr = xin + ((size_t)b*65536 + (size_t)h0*256 + w0)*96;
        float vals[24], s = 0.f, ss = 0.f;
        #pragma unroll
        for (int j = 0; j < 24; j++) {
            float v = xr[l4 + 4*j]; vals[j] = v; s += v; ss += v*v;
        }
        s  += __shfl_xor_sync(0xffffffffu, s, 1);
        s  += __shfl_xor_sync(0xffffffffu, s, 2);
        ss += __shfl_xor_sync(0xffffffffu, ss, 1);
        ss += __shfl_xor_sync(0xffffffffu, ss, 2);
        float mean = s * (1.f/96.f);
        float rstd = rsqrtf(ss * (1.f/96.f) - mean*mean + 1e-5f);
        #pragma unroll
        for (int j = 0; j < 24; j++) {
            int c = l4 + 4*j;
            xs[t*96 + SWZ(t, c)] = tf32f((vals[j]-mean)*rstd*g1[c] + bb1[c]);
        }
    }
    __syncthreads();

    // ---------- phase 2: QKV GEMM ----------
    {
        unsigned Af[12][4];
        #pragma unroll
        for (int kk = 0; kk < 12; kk++) {
            int c0 = kk*8 + tg;
            Af[kk][0] = __float_as_uint(xs[(m0+g)*96   + (c0 ^ sw)]);
            Af[kk][1] = __float_as_uint(xs[(m0+g+8)*96 + (c0 ^ sw)]);
            Af[kk][2] = __float_as_uint(xs[(m0+g)*96   + ((c0+4) ^ sw)]);
            Af[kk][3] = __float_as_uint(xs[(m0+g+8)*96 + ((c0+4) ^ sw)]);
        }
        for (int s3 = 0; s3 < 3; s3++) {
            float acc[6][4];
            #pragma unroll
            for (int i = 0; i < 6; i++) { acc[i][0]=acc[i][1]=acc[i][2]=acc[i][3]=0.f; }
            for (int kk = 0; kk < 12; kk++) {
                #pragma unroll
                for (int nt = 0; nt < 6; nt++) {
                    int ntg = s3*12 + wn*6 + nt;
                    float2 bv = *(const float2*)&wqkv[((ntg*12 + kk)*32 + lane)*2];
                    unsigned bb[2] = { __float_as_uint(bv.x), __float_as_uint(bv.y) };
                    mma_tf32(acc[nt], Af[kk], bb);
                }
            }
            #pragma unroll
            for (int nt = 0; nt < 6; nt++) {
                #pragma unroll
                for (int i = 0; i < 2; i++) {
                    #pragma unroll
                    for (int j = 0; j < 2; j++) {
                        int ncol = wn*48 + nt*8 + 2*tg + j;
                        int c = s3*96 + ncol;          // direct col in [64][288] plane
                        int m = m0 + g + i*8;
                        float v = acc[nt][i*2+j] + __ldg(&qkvb[s3*96 + ncol]);
                        if (s3 == 0) v *= 0.25f;
                        qk[m*288 + (c ^ sw)] = tf32f(v);
                    }
                }
            }
        }
    }
    __syncthreads();

    // ---------- phase 3: per-head attention (round-4 structure) ----------
    for (int h = 0; h < 6; h++) {
        // scores: warp tile [m0,m0+16) x [wn*32, wn*32+32)
        {
            unsigned Aq[2][4];
            #pragma unroll
            for (int kk = 0; kk < 2; kk++) {
                int c0 = h*16 + kk*8 + tg;
                Aq[kk][0] = __float_as_uint(qk[(m0+g)*288   + (c0 ^ sw)]);
                Aq[kk][1] = __float_as_uint(qk[(m0+g+8)*288 + (c0 ^ sw)]);
                Aq[kk][2] = __float_as_uint(qk[(m0+g)*288   + ((c0+4) ^ sw)]);
                Aq[kk][3] = __float_as_uint(qk[(m0+g+8)*288 + ((c0+4) ^ sw)]);
            }
            float acc[4][4];
            #pragma unroll
            for (int i = 0; i < 4; i++) { acc[i][0]=acc[i][1]=acc[i][2]=acc[i][3]=0.f; }
            #pragma unroll
            for (int kk = 0; kk < 2; kk++) {
                #pragma unroll
                for (int nt = 0; nt < 4; nt++) {
                    int u = wn*32 + nt*8 + g;          // k row; u&7 == g
                    int ck = 96 + h*16 + kk*8 + tg;
                    unsigned bb[2] = {
                        __float_as_uint(qk[u*288 + (ck ^ sw)]),
                        __float_as_uint(qk[u*288 + ((ck+4) ^ sw)]) };
                    mma_tf32(acc[nt], Aq[kk], bb);
                }
            }
            #pragma unroll
            for (int nt = 0; nt < 4; nt++) {
                #pragma unroll
                for (int i = 0; i < 2; i++) {
                    #pragma unroll
                    for (int j = 0; j < 2; j++) {
                        int t = m0 + g + i*8;
                        int u = wn*32 + nt*8 + 2*tg + j;
                        int ti = t>>3, tj = t&7, ui = u>>3, uj = u&7;
                        float d = acc[nt][i*2+j]
                                + __ldg(&rpb[((ti-ui+7)*15 + (tj-uj+7))*6 + h]);
                        if (shift) {
                            int hrt = wh*8+ti, wrt = ww*8+tj;
                            int hru = wh*8+ui, wru = ww*8+uj;
                            int rt = (hrt<248?0:(hrt<252?1:2))*3 + (wrt<248?0:(wrt<252?1:2));
                            int ru = (hru<248?0:(hru<252?1:2))*3 + (wru<248?0:(wru<252?1:2));
                            if (rt != ru) d -= 100.f;
                        }
                        sc[t*64 + (u ^ sw)] = d;
                    }
                }
            }
        }
        __syncthreads();

        // softmax: 4 lanes per row
        {
            int t = tid >> 2, l4 = tid & 3;
            int swt = (t & 7) << 2;
            float mx = -1e30f;
            #pragma unroll
            for (int j = 0; j < 16; j++)
                mx = fmaxf(mx, sc[t*64 + ((l4 + 4*j) ^ swt)]);
            mx = fmaxf(mx, __shfl_xor_sync(0xffffffffu, mx, 1));
            mx = fmaxf(mx, __shfl_xor_sync(0xffffffffu, mx, 2));
            float ev[16], sum = 0.f;
            #pragma unroll
            for (int j = 0; j < 16; j++) {
                float e = __expf(sc[t*64 + ((l4 + 4*j) ^ swt)] - mx);
                ev[j] = e; sum += e;
            }
            sum += __shfl_xor_sync(0xffffffffu, sum, 1);
            sum += __shfl_xor_sync(0xffffffffu, sum, 2);
            float inv = 1.f / sum;
            #pragma unroll
            for (int j = 0; j < 16; j++)
                sc[t*64 + ((l4 + 4*j) ^ swt)] = tf32f(ev[j]*inv);
        }
        __syncthreads();

        // AV: warp tile [m0,m0+16) x [wn*8, wn*8+8), K=64
        {
            float av[4] = {0.f, 0.f, 0.f, 0.f};
            int n0 = wn * 8;
            #pragma unroll
            for (int kk = 0; kk < 8; kk++) {
                int c0 = kk*8 + tg;
                unsigned Ap[4] = {
                    __float_as_uint(sc[(m0+g)*64   + (c0 ^ sw)]),
                    __float_as_uint(sc[(m0+g+8)*64 + (c0 ^ sw)]),
                    __float_as_uint(sc[(m0+g)*64   + ((c0+4) ^ sw)]),
                    __float_as_uint(sc[(m0+g+8)*64 + ((c0+4) ^ sw)]) };
                int u  = kk*8 + tg;                    // v rows; u&7 == tg, (u+4)&7 == tg+4
                int cv = 192 + h*16 + n0 + g;
                unsigned bb[2] = {
                    __float_as_uint(qk[u*288     + SWZ(u,   cv)]),
                    __float_as_uint(qk[(u+4)*288 + SWZ(u+4, cv)]) };
                mma_tf32(av, Ap, bb);
            }
            #pragma unroll
            for (int i = 0; i < 2; i++)
                #pragma unroll
                for (int j = 0; j < 2; j++) {
                    int m = m0 + g + i*8;
                    int c = h*16 + n0 + 2*tg + j;
                    xs[m*96 + (c ^ sw)] = tf32f(av[i*2+j]);
                }
        }
        __syncthreads();
    }

    // ---------- phase 4: proj + residual -> gmem ----------
    {
        unsigned Ac[12][4];
        #pragma unroll
        for (int kk = 0; kk < 12; kk++) {
            int c0 = kk*8 + tg;
            Ac[kk][0] = __float_as_uint(xs[(m0+g)*96   + (c0 ^ sw)]);
            Ac[kk][1] = __float_as_uint(xs[(m0+g+8)*96 + (c0 ^ sw)]);
            Ac[kk][2] = __float_as_uint(xs[(m0+g)*96   + ((c0+4) ^ sw)]);
            Ac[kk][3] = __float_as_uint(xs[(m0+g+8)*96 + ((c0+4) ^ sw)]);
        }
        float acc[6][4];
        #pragma unroll
        for (int i = 0; i < 6; i++) { acc[i][0]=acc[i][1]=acc[i][2]=acc[i][3]=0.f; }
        for (int kk = 0; kk < 12; kk++) {
            #pragma unroll
            for (int nt = 0; nt < 6; nt++) {
                int ntg = wn*6 + nt;
                float2 bv = *(const float2*)&wproj[((ntg*12 + kk)*32 + lane)*2];
                unsigned bb[2] = { __float_as_uint(bv.x), __float_as_uint(bv.y) };
                mma_tf32(acc[nt], Ac[kk], bb);
            }
        }
        #pragma unroll
        for (int nt = 0; nt < 6; nt++) {
            #pragma unroll
            for (int i = 0; i < 2; i++) {
                int ncol0 = wn*48 + nt*8 + 2*tg;
                int m = m0 + g + i*8;
                int th = m >> 3, tw = m & 7;
                int h0 = (wh*8 + th + shift) & 255;
                int w0 = (ww*8 + tw + shift) & 255;
                size_t row = ((size_t)b*65536 + (size_t)h0*256 + w0)*96;
                float2 rr = *(const float2*)&xin[row + ncol0];
                float2 o;
                o.x = rr.x + acc[nt][i*2]   + __ldg(&projb[ncol0]);
                o.y = rr.y + acc[nt][i*2+1] + __ldg(&projb[ncol0+1]);
                *(float2*)&xout[row + ncol0] = o;
            }
        }
    }
}

// ======================= MLP kernel (round-4 verbatim, measured good) =======================
// smem: xs[64*100]=6400 | yb[64*100]=6400
#define MLP_SMEM_FLOATS (6400 + 6400)

__global__ void __launch_bounds__(256, 2) mlp_kernel(
    const float* __restrict__ xin, float* __restrict__ xout,
    const float* __restrict__ g2, const float* __restrict__ bb2,
    const float* __restrict__ w1p, const float* __restrict__ b1v,
    const float* __restrict__ w2p, const float* __restrict__ b2v)
{
    extern __shared__ float sm[];
    float* xs = sm;          // 64 x 100 LN'd (tf32)
    float* yb = sm + 6400;   // 64 x 100 gelu(fc1) chunk (tf32)

    const int tid = threadIdx.x, lane = tid & 31, wid = tid >> 5;
    const int g = lane >> 2, tg = lane & 3;
    const int wm = wid >> 1, wn = wid & 1;
    const int m0 = wm * 16;
    const size_t base = (size_t)blockIdx.x * 64 * 96;

    // LN2
    {
        int t = tid >> 2, l4 = tid & 3;
        const float* xr = xin + base + (size_t)t*96;
        float vals[24], s = 0.f, ss = 0.f;
        #pragma unroll
        for (int j = 0; j < 24; j++) {
            float v = xr[l4 + 4*j]; vals[j] = v; s += v; ss += v*v;
        }
        s  += __shfl_xor_sync(0xffffffffu, s, 1);
        s  += __shfl_xor_sync(0xffffffffu, s, 2);
        ss += __shfl_xor_sync(0xffffffffu, ss, 1);
        ss += __shfl_xor_sync(0xffffffffu, ss, 2);
        float mean = s * (1.f/96.f);
        float rstd = rsqrtf(ss * (1.f/96.f) - mean*mean + 1e-5f);
        #pragma unroll
        for (int j = 0; j < 24; j++) {
            int c = l4 + 4*j;
            xs[t*100 + c] = tf32f((vals[j]-mean)*rstd*g2[c] + bb2[c]);
        }
    }
    __syncthreads();

    unsigned Af[12][4];
    #pragma unroll
    for (int kk = 0; kk < 12; kk++) {
        int bse = (m0+g)*100 + kk*8 + tg;
        Af[kk][0] = __float_as_uint(xs[bse]);
        Af[kk][1] = __float_as_uint(xs[bse + 800]);
        Af[kk][2] = __float_as_uint(xs[bse + 4]);
        Af[kk][3] = __float_as_uint(xs[bse + 804]);
    }

    float acc2[6][4];
    #pragma unroll
    for (int i = 0; i < 6; i++) { acc2[i][0]=acc2[i][1]=acc2[i][2]=acc2[i][3]=0.f; }

    for (int ch = 0; ch < 4; ch++) {
        float acc[6][4];
        #pragma unroll
        for (int i = 0; i < 6; i++) { acc[i][0]=acc[i][1]=acc[i][2]=acc[i][3]=0.f; }
        for (int kk = 0; kk < 12; kk++) {
            #pragma unroll
            for (int nt = 0; nt < 6; nt++) {
                int ntg = ch*12 + wn*6 + nt;
                float2 bv = *(const float2*)&w1p[((ntg*12 + kk)*32 + lane)*2];
                unsigned bb[2] = { __float_as_uint(bv.x), __float_as_uint(bv.y) };
                mma_tf32(acc[nt], Af[kk], bb);
            }
        }
        #pragma unroll
        for (int nt = 0; nt < 6; nt++) {
            #pragma unroll
            for (int i = 0; i < 2; i++) {
                #pragma unroll
                for (int j = 0; j < 2; j++) {
                    int c = wn*48 + nt*8 + 2*tg + j;
                    float v = acc[nt][i*2+j] + __ldg(&b1v[ch*96 + c]);
                    v = v * normcdff(v);
                    yb[(m0+g+i*8)*100 + c] = tf32f(v);
                }
            }
        }
        __syncthreads();
        for (int kk = 0; kk < 12; kk++) {
            int bse = (m0+g)*100 + kk*8 + tg;
            unsigned Ay[4] = {
                __float_as_uint(yb[bse]),
                __float_as_uint(yb[bse + 800]),
                __float_as_uint(yb[bse + 4]),
                __float_as_uint(yb[bse + 804]) };
            #pragma unroll
            for (int nt = 0; nt < 6; nt++) {
                int ntg = wn*6 + nt;
                int kkg = ch*12 + kk;
                float2 bv = *(const float2*)&w2p[((ntg*48 + kkg)*32 + lane)*2];
                unsigned bb[2] = { __float_as_uint(bv.x), __float_as_uint(bv.y) };
                mma_tf32(acc2[nt], Ay, bb);
            }
        }
        __syncthreads();
    }

    // residual writeback
    #pragma unroll
    for (int nt = 0; nt < 6; nt++) {
        #pragma unroll
        for (int i = 0; i < 2; i++) {
            int c0 = wn*48 + nt*8 + 2*tg;
            int m = m0 + g + i*8;
            float2 r = *(const float2*)&xin[base + (size_t)m*96 + c0];
            float2 o;
            o.x = r.x + acc2[nt][i*2]   + __ldg(&b2v[c0]);
            o.y = r.y + acc2[nt][i*2+1] + __ldg(&b2v[c0+1]);
            *(float2*)&xout[base + (size_t)m*96 + c0] = o;
        }
    }
}

// ======================= launcher =======================
extern "C" void kernel_launch(void* const* d_in, const int* in_sizes, int n_in,
                              void* d_out, int out_size) {
    const float* x    = (const float*)d_in[0];
    const float* qkvw = (const float*)d_in[1];   // (2,288,96)
    const float* qkvb = (const float*)d_in[2];   // (2,288)
    const float* projw= (const float*)d_in[3];   // (2,96,96)
    const float* projb= (const float*)d_in[4];   // (2,96)
    const float* rpb  = (const float*)d_in[5];   // (2,225,6)
    const float* n1w  = (const float*)d_in[6];
    const float* n1b  = (const float*)d_in[7];
    const float* n2w  = (const float*)d_in[8];
    const float* n2b  = (const float*)d_in[9];
    const float* f1w  = (const float*)d_in[10];  // (2,384,96)
    const float* f1b  = (const float*)d_in[11];  // (2,384)
    const float* f2w  = (const float*)d_in[12];  // (2,96,384)
    const float* f2b  = (const float*)d_in[13];  // (2,96)
    float* out = (float*)d_out;

    float* gw = nullptr;  cudaGetSymbolAddress((void**)&gw, g_w);

    // one merged pack launch for all 8 weight regions
    pack_all<<<(W_ELEMS + 255)/256, 256>>>(qkvw, projw, f1w, f2w, gw);

    const int ATTN_SMEM = ATTN_SMEM_FLOATS * 4;   // 114688 B -> 2 CTAs/SM
    const int MLP_SMEM  = MLP_SMEM_FLOATS * 4;    // 51200 B  -> 2 CTAs/SM
    cudaFuncSetAttribute(attn_kernel, cudaFuncAttributeMaxDynamicSharedMemorySize, ATTN_SMEM);
    cudaFuncSetAttribute(mlp_kernel,  cudaFuncAttributeMaxDynamicSharedMemorySize, MLP_SMEM);

    const int NBLK = 4096;

    // In-place chain (each CTA reads only the tokens it writes; validated R10).
    attn_kernel<<<NBLK, 256, ATTN_SMEM>>>(x, out,
        gw + OFF_QKV0, qkvb, gw + OFF_PROJ0, projb, rpb, n1w, n1b, 0);
    mlp_kernel<<<NBLK, 256, MLP_SMEM>>>(out, out,
        n2w, n2b, gw + OFF_F1_0, f1b, gw + OFF_F2_0, f2b);

    attn_kernel<<<NBLK, 256, ATTN_SMEM>>>(out, out,
        gw + OFF_QKV1, qkvb + 288, gw + OFF_PROJ1, projb + 96,
        rpb + 225*6, n1w + 96, n1b + 96, 4);
    mlp_kernel<<<NBLK, 256, MLP_SMEM>>>(out, out,
        n2w + 96, n2b + 96, gw + OFF_F1_1, f1b + 384, gw + OFF_F2_1, f2b + 96);
}

// round 12
// speedup vs baseline: 2.6267x; 1.7506x over previous
#include <cuda_runtime.h>
#include <math.h>

// Swin stage: B=4, H=W=256, C=96, NH=6, HD=16, WS=8, N=64; 4096 windows.
// Round-11 structure (2 CTAs/SM attn) + bf16 m16n8k16 for weight GEMMs
// (QKV/proj/fc1/fc2); Q@K and P@V stay tf32 on the f32 q/k/v plane.
// Activations packed bf16x2, word-pitch 52 (conflict-free, no XOR math).

#define W_WORDS   110592

__device__ unsigned g_w[W_WORDS];    // packed bf16x2 weights

#define OFF_QKV0   0
#define OFF_QKV1   13824
#define OFF_PROJ0  27648
#define OFF_PROJ1  32256
#define OFF_F1_0   36864
#define OFF_F1_1   55296
#define OFF_F2_0   73728
#define OFF_F2_1   92160

__device__ __forceinline__ unsigned f2tf(float f) {
    unsigned u; asm("cvt.rna.tf32.f32 %0, %1;" : "=r"(u) : "f"(f)); return u;
}
__device__ __forceinline__ float tf32f(float f) {
    return __uint_as_float(f2tf(f));
}
__device__ __forceinline__ unsigned pack_bf16x2(float lo, float hi) {
    unsigned r; asm("cvt.rn.bf16x2.f32 %0, %1, %2;" : "=r"(r) : "f"(hi), "f"(lo));
    return r;
}
__device__ __forceinline__ void mma_tf32(float* c, const unsigned* a, const unsigned* b) {
    asm volatile(
        "mma.sync.aligned.m16n8k8.row.col.f32.tf32.tf32.f32 "
        "{%0,%1,%2,%3},{%4,%5,%6,%7},{%8,%9},{%0,%1,%2,%3};\n"
        : "+f"(c[0]), "+f"(c[1]), "+f"(c[2]), "+f"(c[3])
        : "r"(a[0]), "r"(a[1]), "r"(a[2]), "r"(a[3]), "r"(b[0]), "r"(b[1]));
}
__device__ __forceinline__ void mma_bf16(float* c, const unsigned* a, const unsigned* b) {
    asm volatile(
        "mma.sync.aligned.m16n8k16.row.col.f32.bf16.bf16.f32 "
        "{%0,%1,%2,%3},{%4,%5,%6,%7},{%8,%9},{%0,%1,%2,%3};\n"
        : "+f"(c[0]), "+f"(c[1]), "+f"(c[2]), "+f"(c[3])
        : "r"(a[0]), "r"(a[1]), "r"(a[2]), "r"(a[3]), "r"(b[0]), "r"(b[1]));
}

// ---- bf16 weight packer: word[((nt*KS16+kk)*32+lane)*2+j] =
//      {W[n][k0], W[n][k0+1]},  n = nt*8+(lane>>2), k0 = kk*16 + j*8 + 2*(lane&3)
__global__ void pack_all(const float* __restrict__ qkvw, const float* __restrict__ projw,
                         const float* __restrict__ f1w,  const float* __restrict__ f2w,
                         unsigned* __restrict__ dst) {
    int idx = blockIdx.x * 256 + threadIdx.x;
    if (idx >= W_WORDS) return;
    const float* src; int K, local;
    if (idx < 27648)      { int r = idx;          src = qkvw  + (r/13824)*27648; K=96;  local = r % 13824; }
    else if (idx < 36864) { int r = idx - 27648;  src = projw + (r/4608)*9216;   K=96;  local = r % 4608; }
    else if (idx < 73728) { int r = idx - 36864;  src = f1w   + (r/18432)*36864; K=96;  local = r % 18432; }
    else                  { int r = idx - 73728;  src = f2w   + (r/18432)*36864; K=384; local = r % 18432; }
    int j    = local & 1;
    int lane = (local >> 1) & 31;
    int rest = local >> 6;
    int KS16 = K >> 4;
    int kk   = rest % KS16;
    int nt   = rest / KS16;
    int n  = nt * 8 + (lane >> 2);
    int k0 = kk * 16 + j * 8 + 2 * (lane & 3);
    dst[idx] = pack_bf16x2(src[n * K + k0], src[n * K + k0 + 1]);
}

// XOR swizzle for the f32 q/k/v + scores planes (unchanged from R11)
#define SWZ(r, c) ((c) ^ (((r) & 7) << 2))

// ======================= attention kernel =======================
// smem: xsw[64][52] u32 (bf16x2) =3328 | qk[64][288] f32 =18432 | sc[64][64] f32 =4096
// total 25856 words = 103424 B -> 2 CTAs/SM
#define ATTN_SMEM_WORDS (3328 + 18432 + 4096)

__global__ void __launch_bounds__(256, 2) attn_kernel(
    const float* __restrict__ xin, float* __restrict__ xout,
    const unsigned* __restrict__ wqkv, const float* __restrict__ qkvb,
    const unsigned* __restrict__ wproj, const float* __restrict__ projb,
    const float* __restrict__ rpb,
    const float* __restrict__ g1, const float* __restrict__ bb1,
    int shift)
{
    extern __shared__ float sm[];
    unsigned* xsw = (unsigned*)sm;     // [64][52] bf16x2: LN'd x -> attention ctx
    float* qk = sm + 3328;             // [64][288] f32: q(0-95 scaled) k(96-191) v(192-287)
    float* sc = sm + 21760;            // [64][64] f32 scores/probs

    const int tid = threadIdx.x, lane = tid & 31, wid = tid >> 5;
    const int g = lane >> 2, tg = lane & 3;
    const int wm = wid >> 1, wn = wid & 1;
    const int m0 = wm * 16;
    const int sw = g << 2;

    const int win = blockIdx.x;
    const int b = win >> 10, wi = win & 1023, wh = wi >> 5, ww = wi & 31;

    // ---------- phase 1: LN1 (4 threads/token), write bf16x2 words ----------
    {
        int t = tid >> 2, l4 = tid & 3;
        int th = t >> 3, tw = t & 7;
        int h0 = (wh*8 + th + shift) & 255, w0 = (ww*8 + tw + shift) & 255;
        const float* xr = xin + ((size_t)b*65536 + (size_t)h0*256 + w0)*96;
        float v0[12], v1[12], s = 0.f, ss = 0.f;
        #pragma unroll
        for (int jw = 0; jw < 12; jw++) {
            float2 p = *(const float2*)&xr[2*(l4 + 4*jw)];
            v0[jw] = p.x; v1[jw] = p.y;
            s += p.x + p.y; ss += p.x*p.x + p.y*p.y;
        }
        s  += __shfl_xor_sync(0xffffffffu, s, 1);
        s  += __shfl_xor_sync(0xffffffffu, s, 2);
        ss += __shfl_xor_sync(0xffffffffu, ss, 1);
        ss += __shfl_xor_sync(0xffffffffu, ss, 2);
        float mean = s * (1.f/96.f);
        float rstd = rsqrtf(ss * (1.f/96.f) - mean*mean + 1e-5f);
        #pragma unroll
        for (int jw = 0; jw < 12; jw++) {
            int w = l4 + 4*jw;
            int c0 = 2*w;
            float a = (v0[jw]-mean)*rstd*g1[c0]   + bb1[c0];
            float b2 = (v1[jw]-mean)*rstd*g1[c0+1] + bb1[c0+1];
            xsw[t*52 + w] = pack_bf16x2(a, b2);
        }
    }
    __syncthreads();

    // ---------- phase 2: QKV GEMM (bf16 m16n8k16, 6 k-tiles) ----------
    {
        unsigned Af[6][4];
        #pragma unroll
        for (int kk = 0; kk < 6; kk++) {
            int w0 = kk*8 + tg;
            Af[kk][0] = xsw[(m0+g)*52   + w0];
            Af[kk][1] = xsw[(m0+g+8)*52 + w0];
            Af[kk][2] = xsw[(m0+g)*52   + w0 + 4];
            Af[kk][3] = xsw[(m0+g+8)*52 + w0 + 4];
        }
        for (int s3 = 0; s3 < 3; s3++) {
            float acc[6][4];
            #pragma unroll
            for (int i = 0; i < 6; i++) { acc[i][0]=acc[i][1]=acc[i][2]=acc[i][3]=0.f; }
            #pragma unroll
            for (int kk = 0; kk < 6; kk++) {
                #pragma unroll
                for (int nt = 0; nt < 6; nt++) {
                    int ntg = s3*12 + wn*6 + nt;
                    uint2 bv = *(const uint2*)&wqkv[((ntg*6 + kk)*32 + lane)*2];
                    unsigned bb[2] = { bv.x, bv.y };
                    mma_bf16(acc[nt], Af[kk], bb);
                }
            }
            #pragma unroll
            for (int nt = 0; nt < 6; nt++) {
                #pragma unroll
                for (int i = 0; i < 2; i++) {
                    #pragma unroll
                    for (int j = 0; j < 2; j++) {
                        int ncol = wn*48 + nt*8 + 2*tg + j;
                        int c = s3*96 + ncol;
                        int m = m0 + g + i*8;
                        float v = acc[nt][i*2+j] + __ldg(&qkvb[s3*96 + ncol]);
                        if (s3 == 0) v *= 0.25f;
                        qk[m*288 + (c ^ sw)] = tf32f(v);
                    }
                }
            }
        }
    }
    __syncthreads();

    // ---------- phase 3: per-head attention (tf32, unchanged from R11) ----------
    for (int h = 0; h < 6; h++) {
        {
            unsigned Aq[2][4];
            #pragma unroll
            for (int kk = 0; kk < 2; kk++) {
                int c0 = h*16 + kk*8 + tg;
                Aq[kk][0] = __float_as_uint(qk[(m0+g)*288   + (c0 ^ sw)]);
                Aq[kk][1] = __float_as_uint(qk[(m0+g+8)*288 + (c0 ^ sw)]);
                Aq[kk][2] = __float_as_uint(qk[(m0+g)*288   + ((c0+4) ^ sw)]);
                Aq[kk][3] = __float_as_uint(qk[(m0+g+8)*288 + ((c0+4) ^ sw)]);
            }
            float acc[4][4];
            #pragma unroll
            for (int i = 0; i < 4; i++) { acc[i][0]=acc[i][1]=acc[i][2]=acc[i][3]=0.f; }
            #pragma unroll
            for (int kk = 0; kk < 2; kk++) {
                #pragma unroll
                for (int nt = 0; nt < 4; nt++) {
                    int u = wn*32 + nt*8 + g;
                    int ck = 96 + h*16 + kk*8 + tg;
                    unsigned bb[2] = {
                        __float_as_uint(qk[u*288 + (ck ^ sw)]),
                        __float_as_uint(qk[u*288 + ((ck+4) ^ sw)]) };
                    mma_tf32(acc[nt], Aq[kk], bb);
                }
            }
            #pragma unroll
            for (int nt = 0; nt < 4; nt++) {
                #pragma unroll
                for (int i = 0; i < 2; i++) {
                    #pragma unroll
                    for (int j = 0; j < 2; j++) {
                        int t = m0 + g + i*8;
                        int u = wn*32 + nt*8 + 2*tg + j;
                        int ti = t>>3, tj = t&7, ui = u>>3, uj = u&7;
                        float d = acc[nt][i*2+j]
                                + __ldg(&rpb[((ti-ui+7)*15 + (tj-uj+7))*6 + h]);
                        if (shift) {
                            int hrt = wh*8+ti, wrt = ww*8+tj;
                            int hru = wh*8+ui, wru = ww*8+uj;
                            int rt = (hrt<248?0:(hrt<252?1:2))*3 + (wrt<248?0:(wrt<252?1:2));
                            int ru = (hru<248?0:(hru<252?1:2))*3 + (wru<248?0:(wru<252?1:2));
                            if (rt != ru) d -= 100.f;
                        }
                        sc[t*64 + (u ^ sw)] = d;
                    }
                }
            }
        }
        __syncthreads();

        // softmax
        {
            int t = tid >> 2, l4 = tid & 3;
            int swt = (t & 7) << 2;
            float mx = -1e30f;
            #pragma unroll
            for (int j = 0; j < 16; j++)
                mx = fmaxf(mx, sc[t*64 + ((l4 + 4*j) ^ swt)]);
            mx = fmaxf(mx, __shfl_xor_sync(0xffffffffu, mx, 1));
            mx = fmaxf(mx, __shfl_xor_sync(0xffffffffu, mx, 2));
            float ev[16], sum = 0.f;
            #pragma unroll
            for (int j = 0; j < 16; j++) {
                float e = __expf(sc[t*64 + ((l4 + 4*j) ^ swt)] - mx);
                ev[j] = e; sum += e;
            }
            sum += __shfl_xor_sync(0xffffffffu, sum, 1);
            sum += __shfl_xor_sync(0xffffffffu, sum, 2);
            float inv = 1.f / sum;
            #pragma unroll
            for (int j = 0; j < 16; j++)
                sc[t*64 + ((l4 + 4*j) ^ swt)] = tf32f(ev[j]*inv);
        }
        __syncthreads();

        // AV (tf32); output packed bf16x2 into xsw
        {
            float av[4] = {0.f, 0.f, 0.f, 0.f};
            int n0 = wn * 8;
            #pragma unroll
            for (int kk = 0; kk < 8; kk++) {
                int c0 = kk*8 + tg;
                unsigned Ap[4] = {
                    __float_as_uint(sc[(m0+g)*64   + (c0 ^ sw)]),
                    __float_as_uint(sc[(m0+g+8)*64 + (c0 ^ sw)]),
                    __float_as_uint(sc[(m0+g)*64   + ((c0+4) ^ sw)]),
                    __float_as_uint(sc[(m0+g+8)*64 + ((c0+4) ^ sw)]) };
                int u  = kk*8 + tg;
                int cv = 192 + h*16 + n0 + g;
                unsigned bb[2] = {
                    __float_as_uint(qk[u*288     + SWZ(u,   cv)]),
                    __float_as_uint(qk[(u+4)*288 + SWZ(u+4, cv)]) };
                mma_tf32(av, Ap, bb);
            }
            int wv = h*8 + wn*4 + tg;
            #pragma unroll
            for (int i = 0; i < 2; i++) {
                int m = m0 + g + i*8;
                xsw[m*52 + wv] = pack_bf16x2(av[i*2], av[i*2+1]);
            }
        }
        __syncthreads();
    }

    // ---------- phase 4: proj (bf16) + residual -> gmem ----------
    {
        unsigned Ac[6][4];
        #pragma unroll
        for (int kk = 0; kk < 6; kk++) {
            int w0 = kk*8 + tg;
            Ac[kk][0] = xsw[(m0+g)*52   + w0];
            Ac[kk][1] = xsw[(m0+g+8)*52 + w0];
            Ac[kk][2] = xsw[(m0+g)*52   + w0 + 4];
            Ac[kk][3] = xsw[(m0+g+8)*52 + w0 + 4];
        }
        float acc[6][4];
        #pragma unroll
        for (int i = 0; i < 6; i++) { acc[i][0]=acc[i][1]=acc[i][2]=acc[i][3]=0.f; }
        #pragma unroll
        for (int kk = 0; kk < 6; kk++) {
            #pragma unroll
            for (int nt = 0; nt < 6; nt++) {
                int ntg = wn*6 + nt;
                uint2 bv = *(const uint2*)&wproj[((ntg*6 + kk)*32 + lane)*2];
                unsigned bb[2] = { bv.x, bv.y };
                mma_bf16(acc[nt], Ac[kk], bb);
            }
        }
        #pragma unroll
        for (int nt = 0; nt < 6; nt++) {
            #pragma unroll
            for (int i = 0; i < 2; i++) {
                int ncol0 = wn*48 + nt*8 + 2*tg;
                int m = m0 + g + i*8;
                int th = m >> 3, tw = m & 7;
                int h0 = (wh*8 + th + shift) & 255;
                int w0 = (ww*8 + tw + shift) & 255;
                size_t row = ((size_t)b*65536 + (size_t)h0*256 + w0)*96;
                float2 rr = *(const float2*)&xin[row + ncol0];
                float2 o;
                o.x = rr.x + acc[nt][i*2]   + __ldg(&projb[ncol0]);
                o.y = rr.y + acc[nt][i*2+1] + __ldg(&projb[ncol0+1]);
                *(float2*)&xout[row + ncol0] = o;
            }
        }
    }
}

// ======================= MLP kernel (bf16 throughout) =======================
// smem: xsw[64][52] + ybw[64][52] = 6656 words = 26624 B
#define MLP_SMEM_WORDS (3328 + 3328)

__global__ void __launch_bounds__(256, 2) mlp_kernel(
    const float* __restrict__ xin, float* __restrict__ xout,
    const float* __restrict__ g2, const float* __restrict__ bb2,
    const unsigned* __restrict__ w1p, const float* __restrict__ b1v,
    const unsigned* __restrict__ w2p, const float* __restrict__ b2v)
{
    extern __shared__ float sm[];
    unsigned* xsw = (unsigned*)sm;       // [64][52] LN'd (bf16x2)
    unsigned* ybw = (unsigned*)sm + 3328; // [64][52] gelu(fc1) chunk (bf16x2)

    const int tid = threadIdx.x, lane = tid & 31, wid = tid >> 5;
    const int g = lane >> 2, tg = lane & 3;
    const int wm = wid >> 1, wn = wid & 1;
    const int m0 = wm * 16;
    const size_t base = (size_t)blockIdx.x * 64 * 96;

    // LN2 -> bf16x2 words
    {
        int t = tid >> 2, l4 = tid & 3;
        const float* xr = xin + base + (size_t)t*96;
        float v0[12], v1[12], s = 0.f, ss = 0.f;
        #pragma unroll
        for (int jw = 0; jw < 12; jw++) {
            float2 p = *(const float2*)&xr[2*(l4 + 4*jw)];
            v0[jw] = p.x; v1[jw] = p.y;
            s += p.x + p.y; ss += p.x*p.x + p.y*p.y;
        }
        s  += __shfl_xor_sync(0xffffffffu, s, 1);
        s  += __shfl_xor_sync(0xffffffffu, s, 2);
        ss += __shfl_xor_sync(0xffffffffu, ss, 1);
        ss += __shfl_xor_sync(0xffffffffu, ss, 2);
        float mean = s * (1.f/96.f);
        float rstd = rsqrtf(ss * (1.f/96.f) - mean*mean + 1e-5f);
        #pragma unroll
        for (int jw = 0; jw < 12; jw++) {
            int w = l4 + 4*jw;
            int c0 = 2*w;
            float a = (v0[jw]-mean)*rstd*g2[c0]   + bb2[c0];
            float b2 = (v1[jw]-mean)*rstd*g2[c0+1] + bb2[c0+1];
            xsw[t*52 + w] = pack_bf16x2(a, b2);
        }
    }
    __syncthreads();

    unsigned Af[6][4];
    #pragma unroll
    for (int kk = 0; kk < 6; kk++) {
        int w0 = kk*8 + tg;
        Af[kk][0] = xsw[(m0+g)*52   + w0];
        Af[kk][1] = xsw[(m0+g+8)*52 + w0];
        Af[kk][2] = xsw[(m0+g)*52   + w0 + 4];
        Af[kk][3] = xsw[(m0+g+8)*52 + w0 + 4];
    }

    float acc2[6][4];
    #pragma unroll
    for (int i = 0; i < 6; i++) { acc2[i][0]=acc2[i][1]=acc2[i][2]=acc2[i][3]=0.f; }

    for (int ch = 0; ch < 4; ch++) {
        // fc1 chunk (bf16)
        float acc[6][4];
        #pragma unroll
        for (int i = 0; i < 6; i++) { acc[i][0]=acc[i][1]=acc[i][2]=acc[i][3]=0.f; }
        #pragma unroll
        for (int kk = 0; kk < 6; kk++) {
            #pragma unroll
            for (int nt = 0; nt < 6; nt++) {
                int ntg = ch*12 + wn*6 + nt;
                uint2 bv = *(const uint2*)&w1p[((ntg*6 + kk)*32 + lane)*2];
                unsigned bb[2] = { bv.x, bv.y };
                mma_bf16(acc[nt], Af[kk], bb);
            }
        }
        // gelu -> ybw (bf16x2)
        #pragma unroll
        for (int nt = 0; nt < 6; nt++) {
            int wv = wn*24 + nt*4 + tg;
            #pragma unroll
            for (int i = 0; i < 2; i++) {
                int c0 = wn*48 + nt*8 + 2*tg;
                float a = acc[nt][i*2]   + __ldg(&b1v[ch*96 + c0]);
                float b2 = acc[nt][i*2+1] + __ldg(&b1v[ch*96 + c0 + 1]);
                a = a * normcdff(a);
                b2 = b2 * normcdff(b2);
                ybw[(m0+g+i*8)*52 + wv] = pack_bf16x2(a, b2);
            }
        }
        __syncthreads();
        // fc2 partial accumulate (bf16)
        #pragma unroll
        for (int kk = 0; kk < 6; kk++) {
            int w0 = kk*8 + tg;
            unsigned Ay[4] = {
                ybw[(m0+g)*52   + w0],
                ybw[(m0+g+8)*52 + w0],
                ybw[(m0+g)*52   + w0 + 4],
                ybw[(m0+g+8)*52 + w0 + 4] };
            #pragma unroll
            for (int nt = 0; nt < 6; nt++) {
                int ntg = wn*6 + nt;
                int kkg = ch*6 + kk;
                uint2 bv = *(const uint2*)&w2p[((ntg*24 + kkg)*32 + lane)*2];
                unsigned bb[2] = { bv.x, bv.y };
                mma_bf16(acc2[nt], Ay, bb);
            }
        }
        __syncthreads();
    }

    // residual writeback
    #pragma unroll
    for (int nt = 0; nt < 6; nt++) {
        #pragma unroll
        for (int i = 0; i < 2; i++) {
            int c0 = wn*48 + nt*8 + 2*tg;
            int m = m0 + g + i*8;
            float2 r = *(const float2*)&xin[base + (size_t)m*96 + c0];
            float2 o;
            o.x = r.x + acc2[nt][i*2]   + __ldg(&b2v[c0]);
            o.y = r.y + acc2[nt][i*2+1] + __ldg(&b2v[c0+1]);
            *(float2*)&xout[base + (size_t)m*96 + c0] = o;
        }
    }
}

// ======================= launcher =======================
extern "C" void kernel_launch(void* const* d_in, const int* in_sizes, int n_in,
                              void* d_out, int out_size) {
    const float* x    = (const float*)d_in[0];
    const float* qkvw = (const float*)d_in[1];   // (2,288,96)
    const float* qkvb = (const float*)d_in[2];   // (2,288)
    const float* projw= (const float*)d_in[3];   // (2,96,96)
    const float* projb= (const float*)d_in[4];   // (2,96)
    const float* rpb  = (const float*)d_in[5];   // (2,225,6)
    const float* n1w  = (const float*)d_in[6];
    const float* n1b  = (const float*)d_in[7];
    const float* n2w  = (const float*)d_in[8];
    const float* n2b  = (const float*)d_in[9];
    const float* f1w  = (const float*)d_in[10];  // (2,384,96)
    const float* f1b  = (const float*)d_in[11];  // (2,384)
    const float* f2w  = (const float*)d_in[12];  // (2,96,384)
    const float* f2b  = (const float*)d_in[13];  // (2,96)
    float* out = (float*)d_out;

    unsigned* gw = nullptr;  cudaGetSymbolAddress((void**)&gw, g_w);

    pack_all<<<(W_WORDS + 255)/256, 256>>>(qkvw, projw, f1w, f2w, gw);

    const int ATTN_SMEM = ATTN_SMEM_WORDS * 4;   // 103424 B -> 2 CTAs/SM
    const int MLP_SMEM  = MLP_SMEM_WORDS * 4;    // 26624 B
    cudaFuncSetAttribute(attn_kernel, cudaFuncAttributeMaxDynamicSharedMemorySize, ATTN_SMEM);
    cudaFuncSetAttribute(mlp_kernel,  cudaFuncAttributeMaxDynamicSharedMemorySize, MLP_SMEM);

    const int NBLK = 4096;

    attn_kernel<<<NBLK, 256, ATTN_SMEM>>>(x, out,
        gw + OFF_QKV0, qkvb, gw + OFF_PROJ0, projb, rpb, n1w, n1b, 0);
    mlp_kernel<<<NBLK, 256, MLP_SMEM>>>(out, out,
        n2w, n2b, gw + OFF_F1_0, f1b, gw + OFF_F2_0, f2b);

    attn_kernel<<<NBLK, 256, ATTN_SMEM>>>(out, out,
        gw + OFF_QKV1, qkvb + 288, gw + OFF_PROJ1, projb + 96,
        rpb + 225*6, n1w + 96, n1b + 96, 4);
    mlp_kernel<<<NBLK, 256, MLP_SMEM>>>(out, out,
        n2w + 96, n2b + 96, gw + OFF_F1_1, f1b + 384, gw + OFF_F2_1, f2b + 96);
}

// round 13
// speedup vs baseline: 2.8099x; 1.0697x over previous
#include <cuda_runtime.h>
#include <math.h>

// Swin stage: B=4, H=W=256, C=96, NH=6, HD=16, WS=8, N=64; 4096 windows.
// bf16 m16n8k16 everywhere: weight GEMMs (QKV/proj/fc1/fc2) AND the attention
// core (Q@K, P@V). Softmax in f32. q/k bf16-packed along d; V transposed once
// per window into bf16x2 V^T; probs bf16-packed along u.

#define W_WORDS   110592

__device__ unsigned g_w[W_WORDS];    // packed bf16x2 weights

#define OFF_QKV0   0
#define OFF_QKV1   13824
#define OFF_PROJ0  27648
#define OFF_PROJ1  32256
#define OFF_F1_0   36864
#define OFF_F1_1   55296
#define OFF_F2_0   73728
#define OFF_F2_1   92160

__device__ __forceinline__ unsigned pack_bf16x2(float lo, float hi) {
    unsigned r; asm("cvt.rn.bf16x2.f32 %0, %1, %2;" : "=r"(r) : "f"(hi), "f"(lo));
    return r;
}
__device__ __forceinline__ void mma_bf16(float* c, const unsigned* a, const unsigned* b) {
    asm volatile(
        "mma.sync.aligned.m16n8k16.row.col.f32.bf16.bf16.f32 "
        "{%0,%1,%2,%3},{%4,%5,%6,%7},{%8,%9},{%0,%1,%2,%3};\n"
        : "+f"(c[0]), "+f"(c[1]), "+f"(c[2]), "+f"(c[3])
        : "r"(a[0]), "r"(a[1]), "r"(a[2]), "r"(a[3]), "r"(b[0]), "r"(b[1]));
}

// ---- bf16 weight packer (unchanged from R12) ----
__global__ void pack_all(const float* __restrict__ qkvw, const float* __restrict__ projw,
                         const float* __restrict__ f1w,  const float* __restrict__ f2w,
                         unsigned* __restrict__ dst) {
    int idx = blockIdx.x * 256 + threadIdx.x;
    if (idx >= W_WORDS) return;
    const float* src; int K, local;
    if (idx < 27648)      { int r = idx;          src = qkvw  + (r/13824)*27648; K=96;  local = r % 13824; }
    else if (idx < 36864) { int r = idx - 27648;  src = projw + (r/4608)*9216;   K=96;  local = r % 4608; }
    else if (idx < 73728) { int r = idx - 36864;  src = f1w   + (r/18432)*36864; K=96;  local = r % 18432; }
    else                  { int r = idx - 73728;  src = f2w   + (r/18432)*36864; K=384; local = r % 18432; }
    int j    = local & 1;
    int lane = (local >> 1) & 31;
    int rest = local >> 6;
    int KS16 = K >> 4;
    int kk   = rest % KS16;
    int nt   = rest / KS16;
    int n  = nt * 8 + (lane >> 2);
    int k0 = kk * 16 + j * 8 + 2 * (lane & 3);
    dst[idx] = pack_bf16x2(src[n * K + k0], src[n * K + k0 + 1]);
}

#define SWZ_T(c, t) ((c) ^ (((t) & 7) << 2))

// ======================= attention kernel =======================
// smem words: xsw[64][52]=3328 | qkw[64][100]=6400 (q words 0-47, k 48-95)
//   | vtw[96][36]=3456 | sc f32 [64][64]=4096 (XOR) | probw[64][36]=2304
//   | vf f32 [64][97]=6208 aliases sc+probw
// total 19584 words = 78336 B -> 2 CTAs/SM
#define XSW_OFF   0
#define QKW_OFF   3328
#define VTW_OFF   9728
#define SC_OFF    13184
#define PROBW_OFF 17280
#define VF_OFF    13184
#define ATTN_SMEM_WORDS 19584

__global__ void __launch_bounds__(256, 2) attn_kernel(
    const float* __restrict__ xin, float* __restrict__ xout,
    const unsigned* __restrict__ wqkv, const float* __restrict__ qkvb,
    const unsigned* __restrict__ wproj, const float* __restrict__ projb,
    const float* __restrict__ rpb,
    const float* __restrict__ g1, const float* __restrict__ bb1,
    int shift)
{
    extern __shared__ float sm[];
    unsigned* xsw   = (unsigned*)sm + XSW_OFF;
    unsigned* qkw   = (unsigned*)sm + QKW_OFF;
    unsigned* vtw   = (unsigned*)sm + VTW_OFF;
    float*    sc    = sm + SC_OFF;
    unsigned* probw = (unsigned*)sm + PROBW_OFF;
    float*    vf    = sm + VF_OFF;

    const int tid = threadIdx.x, lane = tid & 31, wid = tid >> 5;
    const int g = lane >> 2, tg = lane & 3;
    const int wm = wid >> 1, wn = wid & 1;
    const int m0 = wm * 16;

    const int win = blockIdx.x;
    const int b = win >> 10, wi = win & 1023, wh = wi >> 5, ww = wi & 31;

    // ---------- phase 1: LN1 -> xsw (bf16x2) ----------
    {
        int t = tid >> 2, l4 = tid & 3;
        int th = t >> 3, tw = t & 7;
        int h0 = (wh*8 + th + shift) & 255, w0 = (ww*8 + tw + shift) & 255;
        const float* xr = xin + ((size_t)b*65536 + (size_t)h0*256 + w0)*96;
        float v0[12], v1[12], s = 0.f, ss = 0.f;
        #pragma unroll
        for (int jw = 0; jw < 12; jw++) {
            float2 p = *(const float2*)&xr[2*(l4 + 4*jw)];
            v0[jw] = p.x; v1[jw] = p.y;
            s += p.x + p.y; ss += p.x*p.x + p.y*p.y;
        }
        s  += __shfl_xor_sync(0xffffffffu, s, 1);
        s  += __shfl_xor_sync(0xffffffffu, s, 2);
        ss += __shfl_xor_sync(0xffffffffu, ss, 1);
        ss += __shfl_xor_sync(0xffffffffu, ss, 2);
        float mean = s * (1.f/96.f);
        float rstd = rsqrtf(ss * (1.f/96.f) - mean*mean + 1e-5f);
        #pragma unroll
        for (int jw = 0; jw < 12; jw++) {
            int w = l4 + 4*jw;
            int c0 = 2*w;
            float a = (v0[jw]-mean)*rstd*g1[c0]   + bb1[c0];
            float b2 = (v1[jw]-mean)*rstd*g1[c0+1] + bb1[c0+1];
            xsw[t*52 + w] = pack_bf16x2(a, b2);
        }
    }
    __syncthreads();

    // ---------- phase 2: QKV GEMM (bf16); q,k -> qkw packed; v -> vf f32 ----------
    {
        unsigned Af[6][4];
        #pragma unroll
        for (int kk = 0; kk < 6; kk++) {
            int w0 = kk*8 + tg;
            Af[kk][0] = xsw[(m0+g)*52   + w0];
            Af[kk][1] = xsw[(m0+g+8)*52 + w0];
            Af[kk][2] = xsw[(m0+g)*52   + w0 + 4];
            Af[kk][3] = xsw[(m0+g+8)*52 + w0 + 4];
        }
        for (int s3 = 0; s3 < 3; s3++) {
            float acc[6][4];
            #pragma unroll
            for (int i = 0; i < 6; i++) { acc[i][0]=acc[i][1]=acc[i][2]=acc[i][3]=0.f; }
            #pragma unroll
            for (int kk = 0; kk < 6; kk++) {
                #pragma unroll
                for (int nt = 0; nt < 6; nt++) {
                    int ntg = s3*12 + wn*6 + nt;
                    uint2 bv = *(const uint2*)&wqkv[((ntg*6 + kk)*32 + lane)*2];
                    unsigned bb[2] = { bv.x, bv.y };
                    mma_bf16(acc[nt], Af[kk], bb);
                }
            }
            #pragma unroll
            for (int nt = 0; nt < 6; nt++) {
                #pragma unroll
                for (int i = 0; i < 2; i++) {
                    int ncol = wn*48 + nt*8 + 2*tg;
                    int m = m0 + g + i*8;
                    float a = acc[nt][i*2]   + __ldg(&qkvb[s3*96 + ncol]);
                    float c2 = acc[nt][i*2+1] + __ldg(&qkvb[s3*96 + ncol + 1]);
                    if (s3 == 0) { a *= 0.25f; c2 *= 0.25f; }
                    if (s3 < 2) {
                        int w = wn*24 + nt*4 + tg;
                        qkw[m*100 + s3*48 + w] = pack_bf16x2(a, c2);
                    } else {
                        vf[m*97 + ncol]     = a;
                        vf[m*97 + ncol + 1] = c2;
                    }
                }
            }
        }
    }
    __syncthreads();

    // ---------- phase 2b: V transpose -> vtw (bf16x2 pairs of tokens) ----------
    for (int idx = tid; idx < 96*32; idx += 256) {
        int d = idx >> 5, uw = idx & 31;
        float a = vf[(2*uw)*97 + d];
        float b2 = vf[(2*uw+1)*97 + d];
        vtw[d*36 + uw] = pack_bf16x2(a, b2);
    }
    __syncthreads();

    // ---------- phase 3: per-head attention (bf16 core) ----------
    for (int h = 0; h < 6; h++) {
        // scores: warp tile [m0,m0+16) x [wn*32, +32), one k-tile (d=16)
        {
            unsigned Aq[4] = {
                qkw[(m0+g)*100   + h*8 + tg],
                qkw[(m0+g+8)*100 + h*8 + tg],
                qkw[(m0+g)*100   + h*8 + tg + 4],
                qkw[(m0+g+8)*100 + h*8 + tg + 4] };
            float acc[4][4];
            #pragma unroll
            for (int i = 0; i < 4; i++) { acc[i][0]=acc[i][1]=acc[i][2]=acc[i][3]=0.f; }
            #pragma unroll
            for (int nt = 0; nt < 4; nt++) {
                int u = wn*32 + nt*8 + g;
                unsigned bb[2] = {
                    qkw[u*100 + 48 + h*8 + tg],
                    qkw[u*100 + 48 + h*8 + tg + 4] };
                mma_bf16(acc[nt], Aq, bb);
            }
            #pragma unroll
            for (int nt = 0; nt < 4; nt++) {
                #pragma unroll
                for (int i = 0; i < 2; i++) {
                    #pragma unroll
                    for (int j = 0; j < 2; j++) {
                        int t = m0 + g + i*8;
                        int u = wn*32 + nt*8 + 2*tg + j;
                        int ti = t>>3, tj = t&7, ui = u>>3, uj = u&7;
                        float d = acc[nt][i*2+j]
                                + __ldg(&rpb[((ti-ui+7)*15 + (tj-uj+7))*6 + h]);
                        if (shift) {
                            int hrt = wh*8+ti, wrt = ww*8+tj;
                            int hru = wh*8+ui, wru = ww*8+uj;
                            int rt = (hrt<248?0:(hrt<252?1:2))*3 + (wrt<248?0:(wrt<252?1:2));
                            int ru = (hru<248?0:(hru<252?1:2))*3 + (wru<248?0:(wru<252?1:2));
                            if (rt != ru) d -= 100.f;
                        }
                        sc[t*64 + SWZ_T(u, t)] = d;
                    }
                }
            }
        }
        __syncthreads();

        // softmax (f32) -> probw (bf16x2 along u)
        {
            int t = tid >> 2, l4 = tid & 3;
            float e0[8], e1[8];
            float mx = -1e30f;
            #pragma unroll
            for (int jw = 0; jw < 8; jw++) {
                int a = SWZ_T(2*(l4 + 4*jw), t);     // even; bit0 preserved
                float2 p = *(const float2*)&sc[t*64 + a];
                e0[jw] = p.x; e1[jw] = p.y;
                mx = fmaxf(mx, fmaxf(p.x, p.y));
            }
            mx = fmaxf(mx, __shfl_xor_sync(0xffffffffu, mx, 1));
            mx = fmaxf(mx, __shfl_xor_sync(0xffffffffu, mx, 2));
            float sum = 0.f;
            #pragma unroll
            for (int jw = 0; jw < 8; jw++) {
                e0[jw] = __expf(e0[jw] - mx);
                e1[jw] = __expf(e1[jw] - mx);
                sum += e0[jw] + e1[jw];
            }
            sum += __shfl_xor_sync(0xffffffffu, sum, 1);
            sum += __shfl_xor_sync(0xffffffffu, sum, 2);
            float inv = 1.f / sum;
            #pragma unroll
            for (int jw = 0; jw < 8; jw++)
                probw[t*36 + l4 + 4*jw] = pack_bf16x2(e0[jw]*inv, e1[jw]*inv);
        }
        __syncthreads();

        // P@V (bf16): warp tile [m0,m0+16) x 8 d-cols, 4 k-tiles of 16 tokens
        {
            float av[4] = {0.f, 0.f, 0.f, 0.f};
            int dc = h*16 + wn*8;
            #pragma unroll
            for (int kk = 0; kk < 4; kk++) {
                unsigned Ap[4] = {
                    probw[(m0+g)*36   + kk*8 + tg],
                    probw[(m0+g+8)*36 + kk*8 + tg],
                    probw[(m0+g)*36   + kk*8 + tg + 4],
                    probw[(m0+g+8)*36 + kk*8 + tg + 4] };
                unsigned bb[2] = {
                    vtw[(dc+g)*36 + kk*8 + tg],
                    vtw[(dc+g)*36 + kk*8 + tg + 4] };
                mma_bf16(av, Ap, bb);
            }
            int wv = h*8 + wn*4 + tg;
            xsw[(m0+g)*52   + wv] = pack_bf16x2(av[0], av[1]);
            xsw[(m0+g+8)*52 + wv] = pack_bf16x2(av[2], av[3]);
        }
        __syncthreads();
    }

    // ---------- phase 4: proj (bf16) + residual -> gmem ----------
    {
        unsigned Ac[6][4];
        #pragma unroll
        for (int kk = 0; kk < 6; kk++) {
            int w0 = kk*8 + tg;
            Ac[kk][0] = xsw[(m0+g)*52   + w0];
            Ac[kk][1] = xsw[(m0+g+8)*52 + w0];
            Ac[kk][2] = xsw[(m0+g)*52   + w0 + 4];
            Ac[kk][3] = xsw[(m0+g+8)*52 + w0 + 4];
        }
        float acc[6][4];
        #pragma unroll
        for (int i = 0; i < 6; i++) { acc[i][0]=acc[i][1]=acc[i][2]=acc[i][3]=0.f; }
        #pragma unroll
        for (int kk = 0; kk < 6; kk++) {
            #pragma unroll
            for (int nt = 0; nt < 6; nt++) {
                int ntg = wn*6 + nt;
                uint2 bv = *(const uint2*)&wproj[((ntg*6 + kk)*32 + lane)*2];
                unsigned bb[2] = { bv.x, bv.y };
                mma_bf16(acc[nt], Ac[kk], bb);
            }
        }
        #pragma unroll
        for (int nt = 0; nt < 6; nt++) {
            #pragma unroll
            for (int i = 0; i < 2; i++) {
                int ncol0 = wn*48 + nt*8 + 2*tg;
                int m = m0 + g + i*8;
                int th = m >> 3, tw = m & 7;
                int h0 = (wh*8 + th + shift) & 255;
                int w0 = (ww*8 + tw + shift) & 255;
                size_t row = ((size_t)b*65536 + (size_t)h0*256 + w0)*96;
                float2 rr = *(const float2*)&xin[row + ncol0];
                float2 o;
                o.x = rr.x + acc[nt][i*2]   + __ldg(&projb[ncol0]);
                o.y = rr.y + acc[nt][i*2+1] + __ldg(&projb[ncol0+1]);
                *(float2*)&xout[row + ncol0] = o;
            }
        }
    }
}

// ======================= MLP kernel (R12 verbatim, measured good) =======================
#define MLP_SMEM_WORDS (3328 + 3328)

__global__ void __launch_bounds__(256, 2) mlp_kernel(
    const float* __restrict__ xin, float* __restrict__ xout,
    const float* __restrict__ g2, const float* __restrict__ bb2,
    const unsigned* __restrict__ w1p, const float* __restrict__ b1v,
    const unsigned* __restrict__ w2p, const float* __restrict__ b2v)
{
    extern __shared__ float sm[];
    unsigned* xsw = (unsigned*)sm;
    unsigned* ybw = (unsigned*)sm + 3328;

    const int tid = threadIdx.x, lane = tid & 31, wid = tid >> 5;
    const int g = lane >> 2, tg = lane & 3;
    const int wm = wid >> 1, wn = wid & 1;
    const int m0 = wm * 16;
    const size_t base = (size_t)blockIdx.x * 64 * 96;

    {
        int t = tid >> 2, l4 = tid & 3;
        const float* xr = xin + base + (size_t)t*96;
        float v0[12], v1[12], s = 0.f, ss = 0.f;
        #pragma unroll
        for (int jw = 0; jw < 12; jw++) {
            float2 p = *(const float2*)&xr[2*(l4 + 4*jw)];
            v0[jw] = p.x; v1[jw] = p.y;
            s += p.x + p.y; ss += p.x*p.x + p.y*p.y;
        }
        s  += __shfl_xor_sync(0xffffffffu, s, 1);
        s  += __shfl_xor_sync(0xffffffffu, s, 2);
        ss += __shfl_xor_sync(0xffffffffu, ss, 1);
        ss += __shfl_xor_sync(0xffffffffu, ss, 2);
        float mean = s * (1.f/96.f);
        float rstd = rsqrtf(ss * (1.f/96.f) - mean*mean + 1e-5f);
        #pragma unroll
        for (int jw = 0; jw < 12; jw++) {
            int w = l4 + 4*jw;
            int c0 = 2*w;
            float a = (v0[jw]-mean)*rstd*g2[c0]   + bb2[c0];
            float b2 = (v1[jw]-mean)*rstd*g2[c0+1] + bb2[c0+1];
            xsw[t*52 + w] = pack_bf16x2(a, b2);
        }
    }
    __syncthreads();

    unsigned Af[6][4];
    #pragma unroll
    for (int kk = 0; kk < 6; kk++) {
        int w0 = kk*8 + tg;
        Af[kk][0] = xsw[(m0+g)*52   + w0];
        Af[kk][1] = xsw[(m0+g+8)*52 + w0];
        Af[kk][2] = xsw[(m0+g)*52   + w0 + 4];
        Af[kk][3] = xsw[(m0+g+8)*52 + w0 + 4];
    }

    float acc2[6][4];
    #pragma unroll
    for (int i = 0; i < 6; i++) { acc2[i][0]=acc2[i][1]=acc2[i][2]=acc2[i][3]=0.f; }

    for (int ch = 0; ch < 4; ch++) {
        float acc[6][4];
        #pragma unroll
        for (int i = 0; i < 6; i++) { acc[i][0]=acc[i][1]=acc[i][2]=acc[i][3]=0.f; }
        #pragma unroll
        for (int kk = 0; kk < 6; kk++) {
            #pragma unroll
            for (int nt = 0; nt < 6; nt++) {
                int ntg = ch*12 + wn*6 + nt;
                uint2 bv = *(const uint2*)&w1p[((ntg*6 + kk)*32 + lane)*2];
                unsigned bb[2] = { bv.x, bv.y };
                mma_bf16(acc[nt], Af[kk], bb);
            }
        }
        #pragma unroll
        for (int nt = 0; nt < 6; nt++) {
            int wv = wn*24 + nt*4 + tg;
            #pragma unroll
            for (int i = 0; i < 2; i++) {
                int c0 = wn*48 + nt*8 + 2*tg;
                float a = acc[nt][i*2]   + __ldg(&b1v[ch*96 + c0]);
                float b2 = acc[nt][i*2+1] + __ldg(&b1v[ch*96 + c0 + 1]);
                a = a * normcdff(a);
                b2 = b2 * normcdff(b2);
                ybw[(m0+g+i*8)*52 + wv] = pack_bf16x2(a, b2);
            }
        }
        __syncthreads();
        #pragma unroll
        for (int kk = 0; kk < 6; kk++) {
            int w0 = kk*8 + tg;
            unsigned Ay[4] = {
                ybw[(m0+g)*52   + w0],
                ybw[(m0+g+8)*52 + w0],
                ybw[(m0+g)*52   + w0 + 4],
                ybw[(m0+g+8)*52 + w0 + 4] };
            #pragma unroll
            for (int nt = 0; nt < 6; nt++) {
                int ntg = wn*6 + nt;
                int kkg = ch*6 + kk;
                uint2 bv = *(const uint2*)&w2p[((ntg*24 + kkg)*32 + lane)*2];
                unsigned bb[2] = { bv.x, bv.y };
                mma_bf16(acc2[nt], Ay, bb);
            }
        }
        __syncthreads();
    }

    #pragma unroll
    for (int nt = 0; nt < 6; nt++) {
        #pragma unroll
        for (int i = 0; i < 2; i++) {
            int c0 = wn*48 + nt*8 + 2*tg;
            int m = m0 + g + i*8;
            float2 r = *(const float2*)&xin[base + (size_t)m*96 + c0];
            float2 o;
            o.x = r.x + acc2[nt][i*2]   + __ldg(&b2v[c0]);
            o.y = r.y + acc2[nt][i*2+1] + __ldg(&b2v[c0+1]);
            *(float2*)&xout[base + (size_t)m*96 + c0] = o;
        }
    }
}

// ======================= launcher =======================
extern "C" void kernel_launch(void* const* d_in, const int* in_sizes, int n_in,
                              void* d_out, int out_size) {
    const float* x    = (const float*)d_in[0];
    const float* qkvw = (const float*)d_in[1];
    const float* qkvb = (const float*)d_in[2];
    const float* projw= (const float*)d_in[3];
    const float* projb= (const float*)d_in[4];
    const float* rpb  = (const float*)d_in[5];
    const float* n1w  = (const float*)d_in[6];
    const float* n1b  = (const float*)d_in[7];
    const float* n2w  = (const float*)d_in[8];
    const float* n2b  = (const float*)d_in[9];
    const float* f1w  = (const float*)d_in[10];
    const float* f1b  = (const float*)d_in[11];
    const float* f2w  = (const float*)d_in[12];
    const float* f2b  = (const float*)d_in[13];
    float* out = (float*)d_out;

    unsigned* gw = nullptr;  cudaGetSymbolAddress((void**)&gw, g_w);

    pack_all<<<(W_WORDS + 255)/256, 256>>>(qkvw, projw, f1w, f2w, gw);

    const int ATTN_SMEM = ATTN_SMEM_WORDS * 4;   // 78336 B -> 2 CTAs/SM
    const int MLP_SMEM  = MLP_SMEM_WORDS * 4;    // 26624 B
    cudaFuncSetAttribute(attn_kernel, cudaFuncAttributeMaxDynamicSharedMemorySize, ATTN_SMEM);
    cudaFuncSetAttribute(mlp_kernel,  cudaFuncAttributeMaxDynamicSharedMemorySize, MLP_SMEM);

    const int NBLK = 4096;

    attn_kernel<<<NBLK, 256, ATTN_SMEM>>>(x, out,
        gw + OFF_QKV0, qkvb, gw + OFF_PROJ0, projb, rpb, n1w, n1b, 0);
    mlp_kernel<<<NBLK, 256, MLP_SMEM>>>(out, out,
        n2w, n2b, gw + OFF_F1_0, f1b, gw + OFF_F2_0, f2b);

    attn_kernel<<<NBLK, 256, ATTN_SMEM>>>(out, out,
        gw + OFF_QKV1, qkvb + 288, gw + OFF_PROJ1, projb + 96,
        rpb + 225*6, n1w + 96, n1b + 96, 4);
    mlp_kernel<<<NBLK, 256, MLP_SMEM>>>(out, out,
        n2w + 96, n2b + 96, gw + OFF_F1_1, f1b + 384, gw + OFF_F2_1, f2b + 96);
}